// round 15
// baseline (speedup 1.0000x reference)
#include <cuda_runtime.h>
#include <cuda_bf16.h>
#include <cstdint>
#include <math.h>

// Problem: hidden_states (64, 577, 1024) fp32 -> out (64, 289, 1024) fp32
#define Bn   64
#define Tn   577
#define Cn   1024
#define NE   288      // even tokens (2,4,...,576) that merge into odds
#define NO   288      // odd tokens (1,3,...,575) = merge destinations
#define TOUT 289
#define BCHUNK 32     // batches per pipeline chunk (2 chunks)
#define CAPL 8        // per-block candidate slots
#define CAP  16       // global candidate slots per row

// ---- static device scratch (no runtime allocation allowed) ----
__device__ float g_anorm [Bn * NE];
__device__ float g_rnormO[Bn * NO];
__device__ float g_lmax  [Bn * NE * 3];     // per-(b,i) local max of each jt block
__device__ int   g_ccnt  [Bn * NE];         // zeroed via cudaMemsetAsync each call
__device__ int   g_cand  [Bn * NE * CAP];
__device__ float g_cval  [Bn * NE * CAP];
__device__ int   g_dst   [Bn * NE];
__device__ int   g_off   [Bn * NO];
__device__ int   g_cnt   [Bn * NO];
__device__ int   g_list  [Bn * NE];

// ---------------- helpers ----------------
__device__ __forceinline__ uint32_t smem_u32(const void* p) {
    uint32_t a;
    asm("{ .reg .u64 t; cvta.to.shared.u64 t, %1; cvt.u32.u64 %0, t; }" : "=r"(a) : "l"(p));
    return a;
}
__device__ __forceinline__ void ldm_x4(uint32_t* r, uint32_t addr) {
    asm volatile("ldmatrix.sync.aligned.m8n8.x4.shared.b16 {%0,%1,%2,%3}, [%4];"
        : "=r"(r[0]), "=r"(r[1]), "=r"(r[2]), "=r"(r[3]) : "r"(addr));
}
__device__ __forceinline__ void ldm_x2(uint32_t* r, uint32_t addr) {
    asm volatile("ldmatrix.sync.aligned.m8n8.x2.shared.b16 {%0,%1}, [%2];"
        : "=r"(r[0]), "=r"(r[1]) : "r"(addr));
}
__device__ __forceinline__ void mma_bf16(float* c, const uint32_t* a, const uint32_t* bfr) {
    asm volatile("mma.sync.aligned.m16n8k16.row.col.f32.bf16.bf16.f32 "
        "{%0,%1,%2,%3}, {%4,%5,%6,%7}, {%8,%9}, {%0,%1,%2,%3};"
        : "+f"(c[0]), "+f"(c[1]), "+f"(c[2]), "+f"(c[3])
        : "r"(a[0]), "r"(a[1]), "r"(a[2]), "r"(a[3]), "r"(bfr[0]), "r"(bfr[1]));
}
__device__ __forceinline__ uint32_t pk(float x, float y) {
    __nv_bfloat162 h = __floats2bfloat162_rn(x, y);
    return *(uint32_t*)&h;
}

// ---------------- K1: 96x96 GEMM + in-block normalize + local candidate windows ----------------
// Block (jt, it, b). All blocks compute sqa/sqb (fixed order -> bitwise identical across
// blocks), so rn_j and |a_i| are available locally. Epilogue: normalize accs, local row
// max lm, collect {j : s~ >= lm - 2B} (superset of the global window since gm >= lm),
// append to the row's global candidate list. Scores never touch gmem.
#define KC   64
#define LDS_STRIDE 72
__global__ __launch_bounds__(256) void k_gemm(const float* __restrict__ X, int b0) {
    __shared__ __align__(16) __nv_bfloat16 sA[96 * LDS_STRIDE];
    __shared__ __align__(16) __nv_bfloat16 sB[96 * LDS_STRIDE];
    __shared__ float s_rn[96];
    __shared__ float s_an[96];
    __shared__ float s_red[96 * 4];
    __shared__ int   s_cnt[96];
    __shared__ int   s_cand[96 * CAPL];
    __shared__ float s_cval[96 * CAPL];

    const int b = blockIdx.z + b0, it = blockIdx.y, jt = blockIdx.x;
    const int tid = threadIdx.x, wid = tid >> 5, lane = tid & 31;
    const int wm = wid >> 2, wn = wid & 3;           // warp grid 2 x 4

    int rowL[3], segL[3];
    #pragma unroll
    for (int u = 0; u < 3; u++) { const int v = tid + u * 256; rowL[u] = v >> 3; segL[u] = v & 7; }

    const float* Arow[3]; const float* Brow[3];
    #pragma unroll
    for (int u = 0; u < 3; u++) {
        Arow[u] = X + ((size_t)b * Tn + 2 * (it * 96 + rowL[u] + 1)) * Cn + segL[u] * 8;  // even token
        Brow[u] = X + ((size_t)b * Tn + 2 * (jt * 96 + rowL[u]) + 1) * Cn + segL[u] * 8;  // odd token
    }

    const uint32_t aBase = smem_u32(sA);
    const uint32_t bBase = smem_u32(sB);
    uint32_t aAddr[3], bAddr[3];
    #pragma unroll
    for (int s = 0; s < 3; s++)
        aAddr[s] = aBase + (((wm * 48 + s * 16 + (lane & 15)) * LDS_STRIDE + (lane >> 4) * 8) << 1);
    #pragma unroll
    for (int p = 0; p < 3; p++)
        bAddr[p] = bBase + (((wn * 24 + p * 8 + (lane & 7)) * LDS_STRIDE + ((lane >> 3) & 1) * 8) << 1);

    float acc[3][3][4];
    #pragma unroll
    for (int s = 0; s < 3; s++)
        #pragma unroll
        for (int p = 0; p < 3; p++)
            #pragma unroll
            for (int e = 0; e < 4; e++) acc[s][p][e] = 0.f;

    float sqa[3] = {0.f, 0.f, 0.f}, sqb[3] = {0.f, 0.f, 0.f};

    float4 pa0[3], pa1[3], pb0[3], pb1[3];
    #pragma unroll
    for (int u = 0; u < 3; u++) {
        pa0[u] = *(const float4*)(Arow[u]);     pa1[u] = *(const float4*)(Arow[u] + 4);
        pb0[u] = *(const float4*)(Brow[u]);     pb1[u] = *(const float4*)(Brow[u] + 4);
    }

    #pragma unroll 1
    for (int kt = 0; kt < Cn / KC; kt++) {
        __syncthreads();                         // previous compute done reading smem
        #pragma unroll
        for (int u = 0; u < 3; u++) {
            uint4 va, vb;
            va.x = pk(pa0[u].x, pa0[u].y); va.y = pk(pa0[u].z, pa0[u].w);
            va.z = pk(pa1[u].x, pa1[u].y); va.w = pk(pa1[u].z, pa1[u].w);
            vb.x = pk(pb0[u].x, pb0[u].y); vb.y = pk(pb0[u].z, pb0[u].w);
            vb.z = pk(pb1[u].x, pb1[u].y); vb.w = pk(pb1[u].z, pb1[u].w);
            *(uint4*)(sA + rowL[u] * LDS_STRIDE + segL[u] * 8) = va;
            *(uint4*)(sB + rowL[u] * LDS_STRIDE + segL[u] * 8) = vb;
            sqa[u] += pa0[u].x*pa0[u].x + pa0[u].y*pa0[u].y + pa0[u].z*pa0[u].z + pa0[u].w*pa0[u].w
                    + pa1[u].x*pa1[u].x + pa1[u].y*pa1[u].y + pa1[u].z*pa1[u].z + pa1[u].w*pa1[u].w;
            sqb[u] += pb0[u].x*pb0[u].x + pb0[u].y*pb0[u].y + pb0[u].z*pb0[u].z + pb0[u].w*pb0[u].w
                    + pb1[u].x*pb1[u].x + pb1[u].y*pb1[u].y + pb1[u].z*pb1[u].z + pb1[u].w*pb1[u].w;
        }
        __syncthreads();
        if (kt < Cn / KC - 1) {                  // prefetch next chunk (latency hidden)
            const int k0 = (kt + 1) * KC;
            #pragma unroll
            for (int u = 0; u < 3; u++) {
                pa0[u] = *(const float4*)(Arow[u] + k0);     pa1[u] = *(const float4*)(Arow[u] + k0 + 4);
                pb0[u] = *(const float4*)(Brow[u] + k0);     pb1[u] = *(const float4*)(Brow[u] + k0 + 4);
            }
        }
        #pragma unroll
        for (int step = 0; step < KC / 16; step++) {
            uint32_t aF[3][4], bF[3][2];
            #pragma unroll
            for (int s = 0; s < 3; s++) ldm_x4(aF[s], aAddr[s] + step * 32);
            #pragma unroll
            for (int p = 0; p < 3; p++) ldm_x2(bF[p], bAddr[p] + step * 32);
            #pragma unroll
            for (int s = 0; s < 3; s++)
                #pragma unroll
                for (int p = 0; p < 3; p++) mma_bf16(acc[s][p], aF[s], bF[p]);
        }
    }

    // ---- local norms (8 consecutive tids share a row; shfl tree over lane&7 group) ----
    #pragma unroll
    for (int u = 0; u < 3; u++) {
        float sa = sqa[u], sb = sqb[u];
        #pragma unroll
        for (int o = 1; o < 8; o <<= 1) {
            sa += __shfl_xor_sync(0xffffffffu, sa, o);
            sb += __shfl_xor_sync(0xffffffffu, sb, o);
        }
        if ((tid & 7) == 0) { s_an[rowL[u]] = sqrtf(sa); s_rn[rowL[u]] = 1.0f / sqrtf(sb); }
    }
    if (tid < 96) s_cnt[tid] = 0;
    __syncthreads();

    // ---- normalize accs (bitwise same values as the R10-14 filter computed) ----
    const int tr = lane >> 2, tc = (lane & 3) * 2;
    float2 rr[3];
    #pragma unroll
    for (int p = 0; p < 3; p++) rr[p] = *(float2*)&s_rn[wn * 24 + p * 8 + tc];
    #pragma unroll
    for (int s = 0; s < 3; s++)
        #pragma unroll
        for (int p = 0; p < 3; p++) {
            acc[s][p][0] *= rr[p].x; acc[s][p][1] *= rr[p].y;
            acc[s][p][2] *= rr[p].x; acc[s][p][3] *= rr[p].y;
        }

    // ---- local row max partials (4 lanes per row -> shfl 1,2 -> s_red[row][wn]) ----
    #pragma unroll
    for (int s = 0; s < 3; s++)
        #pragma unroll
        for (int h = 0; h < 2; h++) {
            float m = -3.0e38f;
            #pragma unroll
            for (int p = 0; p < 3; p++) m = fmaxf(m, fmaxf(acc[s][p][2*h], acc[s][p][2*h+1]));
            m = fmaxf(m, __shfl_xor_sync(0xffffffffu, m, 1));
            m = fmaxf(m, __shfl_xor_sync(0xffffffffu, m, 2));
            if ((lane & 3) == 0) s_red[(wm * 48 + s * 16 + tr + h * 8) * 4 + wn] = m;
        }
    __syncthreads();

    // ---- collect local window {s~ >= lm - 2B}; list order nondeterministic but
    //      consumers are order-invariant ----
    #pragma unroll
    for (int s = 0; s < 3; s++)
        #pragma unroll
        for (int h = 0; h < 2; h++) {
            const int row = wm * 48 + s * 16 + tr + h * 8;
            const float lm = fmaxf(fmaxf(s_red[row * 4 + 0], s_red[row * 4 + 1]),
                                   fmaxf(s_red[row * 4 + 2], s_red[row * 4 + 3]));
            const float thr = lm - 0.012f * s_an[row];     // 2B, B=0.006|a| (bound 0.0041|a|)
            #pragma unroll
            for (int p = 0; p < 3; p++)
                #pragma unroll
                for (int e = 0; e < 2; e++) {
                    const float v = acc[s][p][2*h + e];
                    if (v >= thr) {
                        const int slot = atomicAdd(&s_cnt[row], 1);
                        if (slot < CAPL) {
                            s_cand[row * CAPL + slot] = jt * 96 + wn * 24 + p * 8 + tc + e;
                            s_cval[row * CAPL + slot] = v;
                        }
                    }
                }
        }
    __syncthreads();

    // ---- publish: lm, candidates (global atomic slots), norms ----
    if (tid < 96) {
        const int id = b * NE + it * 96 + tid;
        const float lm = fmaxf(fmaxf(s_red[tid * 4 + 0], s_red[tid * 4 + 1]),
                               fmaxf(s_red[tid * 4 + 2], s_red[tid * 4 + 3]));
        g_lmax[id * 3 + jt] = lm;
        const int lcFull = s_cnt[tid];
        const int lc = (lcFull > CAPL) ? CAPL : lcFull;
        // truncated local list would be silently incomplete -> force overflow instead
        const int add = (lcFull > CAPL) ? (CAP + 1) : lcFull;
        const int base = atomicAdd(&g_ccnt[id], add);
        for (int k = 0; k < lc && base + k < CAP; k++) {
            g_cand[(size_t)id * CAP + base + k] = s_cand[tid * CAPL + k];
            g_cval[(size_t)id * CAP + base + k] = s_cval[tid * CAPL + k];
        }
        if (jt == 0) g_anorm[id] = s_an[tid];
        if (it == 0) g_rnormO[b * NO + jt * 96 + tid] = s_rn[tid];
    }
}

// ---------------- K2: prune to global window + exact fp32 verify ----------------
__device__ __forceinline__ float exact_score(const float4 a[8], const float* __restrict__ pb,
                                             int lane, float rn) {
    float s = 0.f;
    #pragma unroll
    for (int q = 0; q < 8; q++) {
        const float4 v = *(const float4*)(pb + q * 128 + lane * 4);
        s += a[q].x * v.x + a[q].y * v.y + a[q].z * v.z + a[q].w * v.w;
    }
    #pragma unroll
    for (int o = 16; o > 0; o >>= 1) s += __shfl_xor_sync(0xffffffffu, s, o);
    return s * rn;
}

__global__ __launch_bounds__(256) void k_exact(const float* __restrict__ X, int b0) {
    const int w = threadIdx.x >> 5, lane = threadIdx.x & 31;
    const int b = blockIdx.x / 36 + b0, sub = blockIdx.x % 36;
    const int i = sub * 8 + w;
    const int id = b * NE + i;
    const float* Xb = X + (size_t)b * Tn * Cn;

    const int cnt = g_ccnt[id];
    float best = -3.0e38f; int bj = NO;

    if (cnt <= CAP) {
        const float gm = fmaxf(fmaxf(g_lmax[id * 3], g_lmax[id * 3 + 1]), g_lmax[id * 3 + 2]);
        const float thr = gm - 0.012f * g_anorm[id];       // exact same window as R10-14
        int   jv = -1;
        float vv = -3.0e38f;
        if (lane < cnt) { jv = g_cand[(size_t)id * CAP + lane]; vv = g_cval[(size_t)id * CAP + lane]; }
        const unsigned pmask = __ballot_sync(0xffffffffu, lane < cnt && vv >= thr);
        if (__popc(pmask) == 1) {                           // unique window member = proven argmax
            const int src = __ffs(pmask) - 1;
            const int j = __shfl_sync(0xffffffffu, jv, src);
            if (lane == 0) g_dst[id] = j;
            return;
        }
        float4 a[8];
        const float* pa = Xb + (size_t)(2 * i + 2) * Cn;
        #pragma unroll
        for (int q = 0; q < 8; q++) a[q] = *(const float4*)(pa + q * 128 + lane * 4);
        unsigned m = pmask;
        while (m) {
            const int bit = __ffs(m) - 1;
            m &= m - 1;
            const int j = __shfl_sync(0xffffffffu, jv, bit);
            const float v = exact_score(a, Xb + (size_t)(2 * j + 1) * Cn, lane, g_rnormO[b * NO + j]);
            if (v > best || (v == best && j < bj)) { best = v; bj = j; }   // order-invariant
        }
    } else {                                                // overflow: deterministic full scan
        float4 a[8];
        const float* pa = Xb + (size_t)(2 * i + 2) * Cn;
        #pragma unroll
        for (int q = 0; q < 8; q++) a[q] = *(const float4*)(pa + q * 128 + lane * 4);
        for (int j = 0; j < NO; j++) {
            const float v = exact_score(a, Xb + (size_t)(2 * j + 1) * Cn, lane, g_rnormO[b * NO + j]);
            if (v > best || (v == best && j < bj)) { best = v; bj = j; }
        }
    }
    if (lane == 0) g_dst[id] = bj;
}

// ---------------- K3: deterministic CSR build (parallel prefix, no atomics) ----------------
__global__ __launch_bounds__(288) void k_build_csr(int b0) {
    __shared__ int s_dst[NE];
    __shared__ int s_ws[9];
    const int b = blockIdx.x + b0, t = threadIdx.x, wid = t >> 5, lane = t & 31;
    s_dst[t] = g_dst[b * NE + t];
    __syncthreads();

    int c = 0;
    #pragma unroll 4
    for (int i = 0; i < NE; i++) c += (s_dst[i] == t);

    int inc = c;
    #pragma unroll
    for (int o = 1; o < 32; o <<= 1) {
        const int v = __shfl_up_sync(0xffffffffu, inc, o);
        if (lane >= o) inc += v;
    }
    if (lane == 31) s_ws[wid] = inc;
    __syncthreads();
    int wo = 0;
    #pragma unroll
    for (int wv = 0; wv < 9; wv++) wo += (wv < wid) ? s_ws[wv] : 0;
    const int off = wo + inc - c;   // exclusive prefix

    int wv = 0;
    for (int i = 0; i < NE; i++)
        if (s_dst[i] == t) g_list[b * NE + off + (wv++)] = i;   // ascending i
    g_off[b * NO + t] = off;
    g_cnt[b * NO + t] = c;
}

// ---------------- K4: merge via CSR gather ----------------
__global__ __launch_bounds__(256) void k_merge(const float* __restrict__ X, float* __restrict__ out, int b0) {
    const int b = blockIdx.y + b0, row = blockIdx.x, t = threadIdx.x;
    float* orow = out + ((size_t)b * TOUT + row) * Cn;
    const float* Xb = X + (size_t)b * Tn * Cn;

    if (row == 0) {   // lone unm token = original token 0
        *(float4*)(orow + t * 4) = *(const float4*)(Xb + t * 4);
        return;
    }
    const int j   = row - 1;
    const int off = g_off[b * NO + j];
    const int cnt = g_cnt[b * NO + j];

    float4 a = *(const float4*)(Xb + (size_t)(2 * j + 1) * Cn + t * 4);
    for (int s = 0; s < cnt; s++) {
        const int i = g_list[b * NE + off + s];               // ascending i -> fixed fp order
        const float4 v = *(const float4*)(Xb + (size_t)(2 * (i + 1)) * Cn + t * 4);
        a.x += v.x; a.y += v.y; a.z += v.z; a.w += v.w;
    }
    const float inv = 1.0f / (float)(cnt + 1);
    a.x *= inv; a.y *= inv; a.z *= inv; a.w *= inv;
    *(float4*)(orow + t * 4) = a;
}

// ---------------- launch: 2-chunk two-stream pipeline (R14-proven) ----------------
extern "C" void kernel_launch(void* const* d_in, const int* in_sizes, int n_in,
                              void* d_out, int out_size) {
    const float* X = (const float*)d_in[0];
    float* out = (float*)d_out;

    static cudaStream_t s2 = nullptr;
    static cudaEvent_t evG[2], evJ;
    static void* p_ccnt = nullptr;
    if (!s2) {
        cudaStreamCreateWithFlags(&s2, cudaStreamNonBlocking);
        for (int c = 0; c < 2; c++) cudaEventCreateWithFlags(&evG[c], cudaEventDisableTiming);
        cudaEventCreateWithFlags(&evJ, cudaEventDisableTiming);
        cudaGetSymbolAddress(&p_ccnt, g_ccnt);
    }

    cudaMemsetAsync(p_ccnt, 0, Bn * NE * sizeof(int), 0);   // candidates accumulate via atomics

    for (int c = 0; c < 2; c++) {
        const int b0 = c * BCHUNK;
        k_gemm<<<dim3(3, 3, BCHUNK), 256>>>(X, b0);
        cudaEventRecord(evG[c], 0);                       // fork point on capture stream
        cudaStreamWaitEvent(s2, evG[c], 0);
        k_exact    <<<BCHUNK * 36, 256, 0, s2>>>(X, b0);
        k_build_csr<<<BCHUNK, 288, 0, s2>>>(b0);
        k_merge    <<<dim3(TOUT, BCHUNK), 256, 0, s2>>>(X, out, b0);
    }
    cudaEventRecord(evJ, s2);                             // join s2 back
    cudaStreamWaitEvent(0, evJ, 0);
}

// round 16
// speedup vs baseline: 4.7080x; 4.7080x over previous
#include <cuda_runtime.h>
#include <cuda_bf16.h>
#include <cstdint>
#include <math.h>

// Problem: hidden_states (64, 577, 1024) fp32 -> out (64, 289, 1024) fp32
#define Bn   64
#define Tn   577
#define Cn   1024
#define NE   288      // even tokens (2,4,...,576) that merge into odds
#define NO   288      // odd tokens (1,3,...,575) = merge destinations
#define TOUT 289
#define BCHUNK 32     // batches per pipeline chunk (2 chunks)

// ---- static device scratch (no runtime allocation allowed) ----
__device__ float    g_anorm [Bn * NE];
__device__ float    g_rnormO[Bn * NO];
__device__ float    g_lmax  [Bn * NE * 3];      // per-(b,i) local max per jt block
__device__ uint32_t g_maskv [Bn * NE * 9];      // per-(b,i,jt) 96-bit local window mask
__device__ int      g_dst   [Bn * NE];
__device__ int      g_off   [Bn * NO];
__device__ int      g_cnt   [Bn * NO];
__device__ int      g_list  [Bn * NE];

// ---------------- helpers ----------------
__device__ __forceinline__ uint32_t smem_u32(const void* p) {
    uint32_t a;
    asm("{ .reg .u64 t; cvta.to.shared.u64 t, %1; cvt.u32.u64 %0, t; }" : "=r"(a) : "l"(p));
    return a;
}
__device__ __forceinline__ void ldm_x4(uint32_t* r, uint32_t addr) {
    asm volatile("ldmatrix.sync.aligned.m8n8.x4.shared.b16 {%0,%1,%2,%3}, [%4];"
        : "=r"(r[0]), "=r"(r[1]), "=r"(r[2]), "=r"(r[3]) : "r"(addr));
}
__device__ __forceinline__ void ldm_x2(uint32_t* r, uint32_t addr) {
    asm volatile("ldmatrix.sync.aligned.m8n8.x2.shared.b16 {%0,%1}, [%2];"
        : "=r"(r[0]), "=r"(r[1]) : "r"(addr));
}
__device__ __forceinline__ void mma_bf16(float* c, const uint32_t* a, const uint32_t* bfr) {
    asm volatile("mma.sync.aligned.m16n8k16.row.col.f32.bf16.bf16.f32 "
        "{%0,%1,%2,%3}, {%4,%5,%6,%7}, {%8,%9}, {%0,%1,%2,%3};"
        : "+f"(c[0]), "+f"(c[1]), "+f"(c[2]), "+f"(c[3])
        : "r"(a[0]), "r"(a[1]), "r"(a[2]), "r"(a[3]), "r"(bfr[0]), "r"(bfr[1]));
}
__device__ __forceinline__ uint32_t pk(float x, float y) {
    __nv_bfloat162 h = __floats2bfloat162_rn(x, y);
    return *(uint32_t*)&h;
}

// ---------------- K1: 96x96 GEMM + local-window bitmask epilogue ----------------
// Block (jt, it, b). All blocks accumulate sqa/sqb in the same fixed order ->
// rn_j / |a_i| bitwise identical everywhere. Epilogue: normalize accs, local row
// max lm, 96-bit mask {col : s~ >= lm - 2B} via shared atomicOr (deterministic),
// publish lm + 3 mask words per row. Scores never touch gmem.
#define KC   64
#define LDS_STRIDE 72
__global__ __launch_bounds__(256) void k_gemm(const float* __restrict__ X, int b0) {
    __shared__ __align__(16) __nv_bfloat16 sA[96 * LDS_STRIDE];
    __shared__ __align__(16) __nv_bfloat16 sB[96 * LDS_STRIDE];
    __shared__ float    s_rn[96];
    __shared__ float    s_an[96];
    __shared__ float    s_red[96 * 4];
    __shared__ uint32_t s_mask[96 * 3];

    const int b = blockIdx.z + b0, it = blockIdx.y, jt = blockIdx.x;
    const int tid = threadIdx.x, wid = tid >> 5, lane = tid & 31;
    const int wm = wid >> 2, wn = wid & 3;           // warp grid 2 x 4

    int rowL[3], segL[3];
    #pragma unroll
    for (int u = 0; u < 3; u++) { const int v = tid + u * 256; rowL[u] = v >> 3; segL[u] = v & 7; }

    const float* Arow[3]; const float* Brow[3];
    #pragma unroll
    for (int u = 0; u < 3; u++) {
        Arow[u] = X + ((size_t)b * Tn + 2 * (it * 96 + rowL[u] + 1)) * Cn + segL[u] * 8;  // even token
        Brow[u] = X + ((size_t)b * Tn + 2 * (jt * 96 + rowL[u]) + 1) * Cn + segL[u] * 8;  // odd token
    }

    const uint32_t aBase = smem_u32(sA);
    const uint32_t bBase = smem_u32(sB);
    uint32_t aAddr[3], bAddr[3];
    #pragma unroll
    for (int s = 0; s < 3; s++)
        aAddr[s] = aBase + (((wm * 48 + s * 16 + (lane & 15)) * LDS_STRIDE + (lane >> 4) * 8) << 1);
    #pragma unroll
    for (int p = 0; p < 3; p++)
        bAddr[p] = bBase + (((wn * 24 + p * 8 + (lane & 7)) * LDS_STRIDE + ((lane >> 3) & 1) * 8) << 1);

    float acc[3][3][4];
    #pragma unroll
    for (int s = 0; s < 3; s++)
        #pragma unroll
        for (int p = 0; p < 3; p++)
            #pragma unroll
            for (int e = 0; e < 4; e++) acc[s][p][e] = 0.f;

    float sqa[3] = {0.f, 0.f, 0.f}, sqb[3] = {0.f, 0.f, 0.f};

    float4 pa0[3], pa1[3], pb0[3], pb1[3];
    #pragma unroll
    for (int u = 0; u < 3; u++) {
        pa0[u] = *(const float4*)(Arow[u]);     pa1[u] = *(const float4*)(Arow[u] + 4);
        pb0[u] = *(const float4*)(Brow[u]);     pb1[u] = *(const float4*)(Brow[u] + 4);
    }

    #pragma unroll 1
    for (int kt = 0; kt < Cn / KC; kt++) {
        __syncthreads();                         // previous compute done reading smem
        #pragma unroll
        for (int u = 0; u < 3; u++) {
            uint4 va, vb;
            va.x = pk(pa0[u].x, pa0[u].y); va.y = pk(pa0[u].z, pa0[u].w);
            va.z = pk(pa1[u].x, pa1[u].y); va.w = pk(pa1[u].z, pa1[u].w);
            vb.x = pk(pb0[u].x, pb0[u].y); vb.y = pk(pb0[u].z, pb0[u].w);
            vb.z = pk(pb1[u].x, pb1[u].y); vb.w = pk(pb1[u].z, pb1[u].w);
            *(uint4*)(sA + rowL[u] * LDS_STRIDE + segL[u] * 8) = va;
            *(uint4*)(sB + rowL[u] * LDS_STRIDE + segL[u] * 8) = vb;
            sqa[u] += pa0[u].x*pa0[u].x + pa0[u].y*pa0[u].y + pa0[u].z*pa0[u].z + pa0[u].w*pa0[u].w
                    + pa1[u].x*pa1[u].x + pa1[u].y*pa1[u].y + pa1[u].z*pa1[u].z + pa1[u].w*pa1[u].w;
            sqb[u] += pb0[u].x*pb0[u].x + pb0[u].y*pb0[u].y + pb0[u].z*pb0[u].z + pb0[u].w*pb0[u].w
                    + pb1[u].x*pb1[u].x + pb1[u].y*pb1[u].y + pb1[u].z*pb1[u].z + pb1[u].w*pb1[u].w;
        }
        __syncthreads();
        if (kt < Cn / KC - 1) {                  // prefetch next chunk (latency hidden)
            const int k0 = (kt + 1) * KC;
            #pragma unroll
            for (int u = 0; u < 3; u++) {
                pa0[u] = *(const float4*)(Arow[u] + k0);     pa1[u] = *(const float4*)(Arow[u] + k0 + 4);
                pb0[u] = *(const float4*)(Brow[u] + k0);     pb1[u] = *(const float4*)(Brow[u] + k0 + 4);
            }
        }
        #pragma unroll
        for (int step = 0; step < KC / 16; step++) {
            uint32_t aF[3][4], bF[3][2];
            #pragma unroll
            for (int s = 0; s < 3; s++) ldm_x4(aF[s], aAddr[s] + step * 32);
            #pragma unroll
            for (int p = 0; p < 3; p++) ldm_x2(bF[p], bAddr[p] + step * 32);
            #pragma unroll
            for (int s = 0; s < 3; s++)
                #pragma unroll
                for (int p = 0; p < 3; p++) mma_bf16(acc[s][p], aF[s], bF[p]);
        }
    }

    // ---- local norms (8 consecutive tids share a row; shfl tree) ----
    #pragma unroll
    for (int u = 0; u < 3; u++) {
        float sa = sqa[u], sb = sqb[u];
        #pragma unroll
        for (int o = 1; o < 8; o <<= 1) {
            sa += __shfl_xor_sync(0xffffffffu, sa, o);
            sb += __shfl_xor_sync(0xffffffffu, sb, o);
        }
        if ((tid & 7) == 0) { s_an[rowL[u]] = sqrtf(sa); s_rn[rowL[u]] = 1.0f / sqrtf(sb); }
    }
    for (int k = tid; k < 96 * 3; k += 256) s_mask[k] = 0u;
    __syncthreads();

    // ---- normalize accs (same values the R10-14 filter computed) ----
    const int tr = lane >> 2, tc = (lane & 3) * 2;
    float2 rr[3];
    #pragma unroll
    for (int p = 0; p < 3; p++) rr[p] = *(float2*)&s_rn[wn * 24 + p * 8 + tc];
    #pragma unroll
    for (int s = 0; s < 3; s++)
        #pragma unroll
        for (int p = 0; p < 3; p++) {
            acc[s][p][0] *= rr[p].x; acc[s][p][1] *= rr[p].y;
            acc[s][p][2] *= rr[p].x; acc[s][p][3] *= rr[p].y;
        }

    // ---- local row max partials ----
    #pragma unroll
    for (int s = 0; s < 3; s++)
        #pragma unroll
        for (int h = 0; h < 2; h++) {
            float m = -3.0e38f;
            #pragma unroll
            for (int p = 0; p < 3; p++) m = fmaxf(m, fmaxf(acc[s][p][2*h], acc[s][p][2*h+1]));
            m = fmaxf(m, __shfl_xor_sync(0xffffffffu, m, 1));
            m = fmaxf(m, __shfl_xor_sync(0xffffffffu, m, 2));
            if ((lane & 3) == 0) s_red[(wm * 48 + s * 16 + tr + h * 8) * 4 + wn] = m;
        }
    __syncthreads();

    // ---- membership mask {col : s~ >= lm - 2B}, B = 0.006*|a_i| (bound 0.0041) ----
    #pragma unroll
    for (int s = 0; s < 3; s++)
        #pragma unroll
        for (int h = 0; h < 2; h++) {
            const int row = wm * 48 + s * 16 + tr + h * 8;
            const float lm = fmaxf(fmaxf(s_red[row * 4 + 0], s_red[row * 4 + 1]),
                                   fmaxf(s_red[row * 4 + 2], s_red[row * 4 + 3]));
            const float thr = lm - 0.012f * s_an[row];
            uint32_t w0 = 0, w1 = 0, w2 = 0;
            #pragma unroll
            for (int p = 0; p < 3; p++)
                #pragma unroll
                for (int e = 0; e < 2; e++) {
                    if (acc[s][p][2*h + e] >= thr) {
                        const int col = wn * 24 + p * 8 + tc + e;
                        if (col < 32) w0 |= 1u << col;
                        else if (col < 64) w1 |= 1u << (col - 32);
                        else w2 |= 1u << (col - 64);
                    }
                }
            if (w0) atomicOr(&s_mask[row * 3 + 0], w0);
            if (w1) atomicOr(&s_mask[row * 3 + 1], w1);
            if (w2) atomicOr(&s_mask[row * 3 + 2], w2);
        }
    __syncthreads();

    // ---- publish (deterministic) ----
    if (tid < 96) {
        const int id = b * NE + it * 96 + tid;
        const float lm = fmaxf(fmaxf(s_red[tid * 4 + 0], s_red[tid * 4 + 1]),
                               fmaxf(s_red[tid * 4 + 2], s_red[tid * 4 + 3]));
        g_lmax[id * 3 + jt] = lm;
        g_maskv[(size_t)id * 9 + jt * 3 + 0] = s_mask[tid * 3 + 0];
        g_maskv[(size_t)id * 9 + jt * 3 + 1] = s_mask[tid * 3 + 1];
        g_maskv[(size_t)id * 9 + jt * 3 + 2] = s_mask[tid * 3 + 2];
        if (jt == 0) g_anorm[id] = s_an[tid];
        if (it == 0) g_rnormO[b * NO + jt * 96 + tid] = s_rn[tid];
    }
}

// ---------------- K2: block-pruned exact fp32 verify (warp per row) ----------------
__device__ __forceinline__ float exact_score(const float4 a[8], const float* __restrict__ pb,
                                             int lane, float rn) {
    float s = 0.f;
    #pragma unroll
    for (int q = 0; q < 8; q++) {
        const float4 v = *(const float4*)(pb + q * 128 + lane * 4);
        s += a[q].x * v.x + a[q].y * v.y + a[q].z * v.z + a[q].w * v.w;
    }
    #pragma unroll
    for (int o = 16; o > 0; o >>= 1) s += __shfl_xor_sync(0xffffffffu, s, o);
    return s * rn;
}

__global__ __launch_bounds__(256) void k_exact(const float* __restrict__ X, int b0) {
    const int w = threadIdx.x >> 5, lane = threadIdx.x & 31;
    const int b = blockIdx.x / 36 + b0, sub = blockIdx.x % 36;
    const int i = sub * 8 + w;
    const int id = b * NE + i;
    const float* Xb = X + (size_t)b * Tn * Cn;

    const float lm0 = g_lmax[id * 3], lm1 = g_lmax[id * 3 + 1], lm2 = g_lmax[id * 3 + 2];
    const float gm  = fmaxf(fmaxf(lm0, lm1), lm2);
    const float thr = gm - 0.012f * g_anorm[id];          // exact window used since R10
    const bool ok0 = (lm0 >= thr), ok1 = (lm1 >= thr), ok2 = (lm2 >= thr);

    uint32_t mk[9];
    #pragma unroll
    for (int k = 0; k < 9; k++) mk[k] = g_maskv[(size_t)id * 9 + k];

    int total = 0;
    if (ok0) total += __popc(mk[0]) + __popc(mk[1]) + __popc(mk[2]);
    if (ok1) total += __popc(mk[3]) + __popc(mk[4]) + __popc(mk[5]);
    if (ok2) total += __popc(mk[6]) + __popc(mk[7]) + __popc(mk[8]);

    if (total == 1) {            // union is a singleton -> proven argmax, no dots
        if (lane == 0) {
            int bj = 0;
            #pragma unroll
            for (int jt = 0; jt < 3; jt++) {
                const bool ok = (jt == 0) ? ok0 : (jt == 1) ? ok1 : ok2;
                if (!ok) continue;
                #pragma unroll
                for (int ww = 0; ww < 3; ww++)
                    if (mk[jt * 3 + ww]) bj = jt * 96 + ww * 32 + __ffs(mk[jt * 3 + ww]) - 1;
            }
            g_dst[id] = bj;
        }
        return;
    }

    // verify union members exactly (superset of the global window -> exact argmax)
    float4 a[8];
    const float* pa = Xb + (size_t)(2 * i + 2) * Cn;
    #pragma unroll
    for (int q = 0; q < 8; q++) a[q] = *(const float4*)(pa + q * 128 + lane * 4);

    float best = -3.0e38f; int bj = NO;
    #pragma unroll 1
    for (int jt = 0; jt < 3; jt++) {              // ascending jt/word/bit => ascending j
        const bool ok = (jt == 0) ? ok0 : (jt == 1) ? ok1 : ok2;
        if (!ok) continue;
        #pragma unroll 1
        for (int ww = 0; ww < 3; ww++) {
            uint32_t m = mk[jt * 3 + ww];
            while (m) {
                const int bit = __ffs(m) - 1;
                m &= m - 1;
                const int j = jt * 96 + ww * 32 + bit;
                const float v = exact_score(a, Xb + (size_t)(2 * j + 1) * Cn, lane, g_rnormO[b * NO + j]);
                if (v > best) { best = v; bj = j; }   // strict '>' keeps lowest j on tie
            }
        }
    }
    if (lane == 0) g_dst[id] = bj;
}

// ---------------- K3: deterministic CSR build (parallel prefix, no atomics) ----------------
__global__ __launch_bounds__(288) void k_build_csr(int b0) {
    __shared__ int s_dst[NE];
    __shared__ int s_ws[9];
    const int b = blockIdx.x + b0, t = threadIdx.x, wid = t >> 5, lane = t & 31;
    s_dst[t] = g_dst[b * NE + t];
    __syncthreads();

    int c = 0;
    #pragma unroll 4
    for (int i = 0; i < NE; i++) c += (s_dst[i] == t);

    int inc = c;
    #pragma unroll
    for (int o = 1; o < 32; o <<= 1) {
        const int v = __shfl_up_sync(0xffffffffu, inc, o);
        if (lane >= o) inc += v;
    }
    if (lane == 31) s_ws[wid] = inc;
    __syncthreads();
    int wo = 0;
    #pragma unroll
    for (int wv = 0; wv < 9; wv++) wo += (wv < wid) ? s_ws[wv] : 0;
    const int off = wo + inc - c;   // exclusive prefix

    int wv = 0;
    for (int i = 0; i < NE; i++)
        if (s_dst[i] == t) g_list[b * NE + off + (wv++)] = i;   // ascending i
    g_off[b * NO + t] = off;
    g_cnt[b * NO + t] = c;
}

// ---------------- K4: merge via CSR gather (R14 body) ----------------
__global__ __launch_bounds__(256) void k_merge(const float* __restrict__ X, float* __restrict__ out, int b0) {
    const int b = blockIdx.y + b0, row = blockIdx.x, t = threadIdx.x;
    float* orow = out + ((size_t)b * TOUT + row) * Cn;
    const float* Xb = X + (size_t)b * Tn * Cn;

    if (row == 0) {   // lone unm token = original token 0
        *(float4*)(orow + t * 4) = *(const float4*)(Xb + t * 4);
        return;
    }
    const int j   = row - 1;
    const int off = g_off[b * NO + j];
    const int cnt = g_cnt[b * NO + j];

    float4 a = *(const float4*)(Xb + (size_t)(2 * j + 1) * Cn + t * 4);
    for (int s = 0; s < cnt; s++) {
        const int i = g_list[b * NE + off + s];               // ascending i -> fixed fp order
        const float4 v = *(const float4*)(Xb + (size_t)(2 * (i + 1)) * Cn + t * 4);
        a.x += v.x; a.y += v.y; a.z += v.z; a.w += v.w;
    }
    const float inv = 1.0f / (float)(cnt + 1);
    a.x *= inv; a.y *= inv; a.z *= inv; a.w *= inv;
    *(float4*)(orow + t * 4) = a;
}

// ---------------- launch: 2-chunk two-stream pipeline (R14-proven; no memset needed) ----------------
extern "C" void kernel_launch(void* const* d_in, const int* in_sizes, int n_in,
                              void* d_out, int out_size) {
    const float* X = (const float*)d_in[0];
    float* out = (float*)d_out;

    static cudaStream_t s2 = nullptr;
    static cudaEvent_t evG[2], evJ;
    if (!s2) {
        cudaStreamCreateWithFlags(&s2, cudaStreamNonBlocking);
        for (int c = 0; c < 2; c++) cudaEventCreateWithFlags(&evG[c], cudaEventDisableTiming);
        cudaEventCreateWithFlags(&evJ, cudaEventDisableTiming);
    }

    for (int c = 0; c < 2; c++) {
        const int b0 = c * BCHUNK;
        k_gemm<<<dim3(3, 3, BCHUNK), 256>>>(X, b0);
        cudaEventRecord(evG[c], 0);                       // fork point on capture stream
        cudaStreamWaitEvent(s2, evG[c], 0);
        k_exact    <<<BCHUNK * 36, 256, 0, s2>>>(X, b0);
        k_build_csr<<<BCHUNK, 288, 0, s2>>>(b0);
        k_merge    <<<dim3(TOUT, BCHUNK), 256, 0, s2>>>(X, out, b0);
    }
    cudaEventRecord(evJ, s2);                             // join s2 back
    cudaStreamWaitEvent(0, evJ, 0);
}

// round 17
// speedup vs baseline: 4.8383x; 1.0277x over previous
#include <cuda_runtime.h>
#include <cuda_bf16.h>
#include <cstdint>
#include <math.h>

// Problem: hidden_states (64, 577, 1024) fp32 -> out (64, 289, 1024) fp32
#define Bn   64
#define Tn   577
#define Cn   1024
#define NE   288      // even tokens (2,4,...,576) that merge into odds
#define NO   288      // odd tokens (1,3,...,575) = merge destinations
#define TOUT 289
#define BCHUNK 32     // batches per pipeline chunk (2 chunks)

// ---- static device scratch (no runtime allocation allowed) ----
__device__ float g_anorm [Bn * NE];
__device__ float g_rnormO[Bn * NO];
__device__ float g_scores[(size_t)Bn * NE * NO];  // raw bf16-dot scores [b][i][j]
__device__ int   g_dst   [Bn * NE];

// ---------------- helpers ----------------
__device__ __forceinline__ uint32_t smem_u32(const void* p) {
    uint32_t a;
    asm("{ .reg .u64 t; cvta.to.shared.u64 t, %1; cvt.u32.u64 %0, t; }" : "=r"(a) : "l"(p));
    return a;
}
__device__ __forceinline__ void ldm_x4(uint32_t* r, uint32_t addr) {
    asm volatile("ldmatrix.sync.aligned.m8n8.x4.shared.b16 {%0,%1,%2,%3}, [%4];"
        : "=r"(r[0]), "=r"(r[1]), "=r"(r[2]), "=r"(r[3]) : "r"(addr));
}
__device__ __forceinline__ void ldm_x2(uint32_t* r, uint32_t addr) {
    asm volatile("ldmatrix.sync.aligned.m8n8.x2.shared.b16 {%0,%1}, [%2];"
        : "=r"(r[0]), "=r"(r[1]) : "r"(addr));
}
__device__ __forceinline__ void mma_bf16(float* c, const uint32_t* a, const uint32_t* bfr) {
    asm volatile("mma.sync.aligned.m16n8k16.row.col.f32.bf16.bf16.f32 "
        "{%0,%1,%2,%3}, {%4,%5,%6,%7}, {%8,%9}, {%0,%1,%2,%3};"
        : "+f"(c[0]), "+f"(c[1]), "+f"(c[2]), "+f"(c[3])
        : "r"(a[0]), "r"(a[1]), "r"(a[2]), "r"(a[3]), "r"(bfr[0]), "r"(bfr[1]));
}
__device__ __forceinline__ uint32_t pk(float x, float y) {
    __nv_bfloat162 h = __floats2bfloat162_rn(x, y);
    return *(uint32_t*)&h;
}

// ---------------- K1: fused fp32->bf16 GEMM + norms (R14 body, unchanged) ----------------
#define KC   64
#define LDS_STRIDE 72
__global__ __launch_bounds__(256) void k_gemm(const float* __restrict__ X, int b0) {
    __shared__ __align__(16) __nv_bfloat16 sA[96 * LDS_STRIDE];
    __shared__ __align__(16) __nv_bfloat16 sB[96 * LDS_STRIDE];

    const int b = blockIdx.z + b0, it = blockIdx.y, jt = blockIdx.x;
    const int tid = threadIdx.x, wid = tid >> 5, lane = tid & 31;
    const int wm = wid >> 2, wn = wid & 3;           // warp grid 2 x 4

    int rowL[3], segL[3];
    #pragma unroll
    for (int u = 0; u < 3; u++) { const int v = tid + u * 256; rowL[u] = v >> 3; segL[u] = v & 7; }

    const float* Arow[3]; const float* Brow[3];
    #pragma unroll
    for (int u = 0; u < 3; u++) {
        Arow[u] = X + ((size_t)b * Tn + 2 * (it * 96 + rowL[u] + 1)) * Cn + segL[u] * 8;  // even token
        Brow[u] = X + ((size_t)b * Tn + 2 * (jt * 96 + rowL[u]) + 1) * Cn + segL[u] * 8;  // odd token
    }

    const uint32_t aBase = smem_u32(sA);
    const uint32_t bBase = smem_u32(sB);
    uint32_t aAddr[3], bAddr[3];
    #pragma unroll
    for (int s = 0; s < 3; s++)
        aAddr[s] = aBase + (((wm * 48 + s * 16 + (lane & 15)) * LDS_STRIDE + (lane >> 4) * 8) << 1);
    #pragma unroll
    for (int p = 0; p < 3; p++)
        bAddr[p] = bBase + (((wn * 24 + p * 8 + (lane & 7)) * LDS_STRIDE + ((lane >> 3) & 1) * 8) << 1);

    float acc[3][3][4];
    #pragma unroll
    for (int s = 0; s < 3; s++)
        #pragma unroll
        for (int p = 0; p < 3; p++)
            #pragma unroll
            for (int e = 0; e < 4; e++) acc[s][p][e] = 0.f;

    float sqa[3] = {0.f, 0.f, 0.f}, sqb[3] = {0.f, 0.f, 0.f};
    const bool doA = (jt == 0), doB = (it == 0);

    float4 pa0[3], pa1[3], pb0[3], pb1[3];
    #pragma unroll
    for (int u = 0; u < 3; u++) {
        pa0[u] = *(const float4*)(Arow[u]);     pa1[u] = *(const float4*)(Arow[u] + 4);
        pb0[u] = *(const float4*)(Brow[u]);     pb1[u] = *(const float4*)(Brow[u] + 4);
    }

    #pragma unroll 1
    for (int kt = 0; kt < Cn / KC; kt++) {
        __syncthreads();                         // previous compute done reading smem
        #pragma unroll
        for (int u = 0; u < 3; u++) {
            uint4 va, vb;
            va.x = pk(pa0[u].x, pa0[u].y); va.y = pk(pa0[u].z, pa0[u].w);
            va.z = pk(pa1[u].x, pa1[u].y); va.w = pk(pa1[u].z, pa1[u].w);
            vb.x = pk(pb0[u].x, pb0[u].y); vb.y = pk(pb0[u].z, pb0[u].w);
            vb.z = pk(pb1[u].x, pb1[u].y); vb.w = pk(pb1[u].z, pb1[u].w);
            *(uint4*)(sA + rowL[u] * LDS_STRIDE + segL[u] * 8) = va;
            *(uint4*)(sB + rowL[u] * LDS_STRIDE + segL[u] * 8) = vb;
            if (doA) sqa[u] += pa0[u].x*pa0[u].x + pa0[u].y*pa0[u].y + pa0[u].z*pa0[u].z + pa0[u].w*pa0[u].w
                             + pa1[u].x*pa1[u].x + pa1[u].y*pa1[u].y + pa1[u].z*pa1[u].z + pa1[u].w*pa1[u].w;
            if (doB) sqb[u] += pb0[u].x*pb0[u].x + pb0[u].y*pb0[u].y + pb0[u].z*pb0[u].z + pb0[u].w*pb0[u].w
                             + pb1[u].x*pb1[u].x + pb1[u].y*pb1[u].y + pb1[u].z*pb1[u].z + pb1[u].w*pb1[u].w;
        }
        __syncthreads();
        if (kt < Cn / KC - 1) {                  // prefetch next chunk (latency hidden)
            const int k0 = (kt + 1) * KC;
            #pragma unroll
            for (int u = 0; u < 3; u++) {
                pa0[u] = *(const float4*)(Arow[u] + k0);     pa1[u] = *(const float4*)(Arow[u] + k0 + 4);
                pb0[u] = *(const float4*)(Brow[u] + k0);     pb1[u] = *(const float4*)(Brow[u] + k0 + 4);
            }
        }
        #pragma unroll
        for (int step = 0; step < KC / 16; step++) {
            uint32_t aF[3][4], bF[3][2];
            #pragma unroll
            for (int s = 0; s < 3; s++) ldm_x4(aF[s], aAddr[s] + step * 32);
            #pragma unroll
            for (int p = 0; p < 3; p++) ldm_x2(bF[p], bAddr[p] + step * 32);
            #pragma unroll
            for (int s = 0; s < 3; s++)
                #pragma unroll
                for (int p = 0; p < 3; p++) mma_bf16(acc[s][p], aF[s], bF[p]);
        }
    }

    if (doA) {
        #pragma unroll
        for (int u = 0; u < 3; u++) {
            float s = sqa[u];
            #pragma unroll
            for (int o = 1; o < 8; o <<= 1) s += __shfl_xor_sync(0xffffffffu, s, o);
            if ((lane & 7) == 0) g_anorm[b * NE + it * 96 + rowL[u]] = sqrtf(s);
        }
    }
    if (doB) {
        #pragma unroll
        for (int u = 0; u < 3; u++) {
            float s = sqb[u];
            #pragma unroll
            for (int o = 1; o < 8; o <<= 1) s += __shfl_xor_sync(0xffffffffu, s, o);
            if ((lane & 7) == 0) g_rnormO[b * NO + jt * 96 + rowL[u]] = 1.0f / sqrtf(s);
        }
    }

    float* sc = g_scores + ((size_t)b * NE + it * 96) * NO + jt * 96;
    const int tr = lane >> 2, tc = (lane & 3) * 2;
    #pragma unroll
    for (int s = 0; s < 3; s++) {
        #pragma unroll
        for (int p = 0; p < 3; p++) {
            const int r0 = wm * 48 + s * 16 + tr;
            const int c  = wn * 24 + p * 8 + tc;
            *(float2*)(sc + (size_t)r0 * NO + c)       = make_float2(acc[s][p][0], acc[s][p][1]);
            *(float2*)(sc + (size_t)(r0 + 8) * NO + c) = make_float2(acc[s][p][2], acc[s][p][3]);
        }
    }
}

// ---------------- K2: candidate filter + pairwise exact fp32 re-verify ----------------
// Same window/decisions as R10-14 (thr = max - 0.012*|a_i|; rigorous bound 0.0082).
// Candidates are verified two at a time (loads of both rows in flight, interleaved
// shfl reductions), compared in ascending-j order with strict '>' -> identical dst.
__device__ __forceinline__ void dot2(const float4 a[8], const float* __restrict__ p0,
                                     const float* __restrict__ p1, int lane,
                                     float& s0o, float& s1o) {
    float s0 = 0.f, s1 = 0.f;
    #pragma unroll
    for (int q = 0; q < 8; q++) {
        const float4 v0 = *(const float4*)(p0 + q * 128 + lane * 4);
        const float4 v1 = *(const float4*)(p1 + q * 128 + lane * 4);
        s0 += a[q].x * v0.x + a[q].y * v0.y + a[q].z * v0.z + a[q].w * v0.w;
        s1 += a[q].x * v1.x + a[q].y * v1.y + a[q].z * v1.z + a[q].w * v1.w;
    }
    #pragma unroll
    for (int o = 16; o > 0; o >>= 1) {
        s0 += __shfl_xor_sync(0xffffffffu, s0, o);
        s1 += __shfl_xor_sync(0xffffffffu, s1, o);
    }
    s0o = s0; s1o = s1;
}
__device__ __forceinline__ float dot1(const float4 a[8], const float* __restrict__ pb, int lane) {
    float s = 0.f;
    #pragma unroll
    for (int q = 0; q < 8; q++) {
        const float4 v = *(const float4*)(pb + q * 128 + lane * 4);
        s += a[q].x * v.x + a[q].y * v.y + a[q].z * v.z + a[q].w * v.w;
    }
    #pragma unroll
    for (int o = 16; o > 0; o >>= 1) s += __shfl_xor_sync(0xffffffffu, s, o);
    return s;
}

__global__ __launch_bounds__(256) void k_filter_exact(const float* __restrict__ X, int b0) {
    const int w = threadIdx.x >> 5, lane = threadIdx.x & 31;
    const int b = blockIdx.x / 36 + b0, sub = blockIdx.x % 36;
    const int i = sub * 8 + w;
    const float* Xb = X + (size_t)b * Tn * Cn;

    const float* srow = g_scores + ((size_t)b * NE + i) * NO;
    const float* rnb  = g_rnormO + b * NO;
    float sc[9];
    #pragma unroll
    for (int q = 0; q < 9; q++) sc[q] = srow[q * 32 + lane] * rnb[q * 32 + lane];

    float m = sc[0];
    #pragma unroll
    for (int q = 1; q < 9; q++) m = fmaxf(m, sc[q]);
    #pragma unroll
    for (int o = 16; o > 0; o >>= 1) m = fmaxf(m, __shfl_xor_sync(0xffffffffu, m, o));
    const float thr = m - 0.012f * g_anorm[b * NE + i];

    unsigned masks[9]; int tot = 0;
    #pragma unroll
    for (int q = 0; q < 9; q++) { masks[q] = __ballot_sync(0xffffffffu, sc[q] >= thr); tot += __popc(masks[q]); }

    if (tot == 1) {            // decided by the error bound alone — no dots needed
        if (lane == 0) {
            int bj = 0;
            #pragma unroll
            for (int q = 0; q < 9; q++) if (masks[q]) bj = q * 32 + __ffs(masks[q]) - 1;
            g_dst[b * NE + i] = bj;
        }
        return;
    }

    float4 a[8];
    const float* pa = Xb + (size_t)(2 * i + 2) * Cn;
    #pragma unroll
    for (int q = 0; q < 8; q++) a[q] = *(const float4*)(pa + q * 128 + lane * 4);

    float best = -3.0e38f; int bj = 0;
    int jprev = -1;
    #pragma unroll 1
    for (int q = 0; q < 9; q++) {                 // ascending q, ascending bit => ascending j
        unsigned mask = masks[q];
        while (mask) {
            const int bit = __ffs(mask) - 1;
            mask &= mask - 1;
            const int j = q * 32 + bit;
            if (jprev < 0) { jprev = j; continue; }
            float v0, v1;
            dot2(a, Xb + (size_t)(2 * jprev + 1) * Cn, Xb + (size_t)(2 * j + 1) * Cn, lane, v0, v1);
            v0 *= rnb[jprev]; v1 *= rnb[j];
            if (v0 > best) { best = v0; bj = jprev; }   // jprev < j: ascending, strict '>'
            if (v1 > best) { best = v1; bj = j; }
            jprev = -1;
        }
    }
    if (jprev >= 0) {
        const float v = dot1(a, Xb + (size_t)(2 * jprev + 1) * Cn, lane) * rnb[jprev];
        if (v > best) { best = v; bj = jprev; }
    }
    if (lane == 0) g_dst[b * NE + i] = bj;
}

// ---------------- K3: merge with in-block ballot CSR (no separate csr kernel) ----------------
// Warp 0 rebuilds row j's ascending source list from g_dst via 9 ballots + prefix
// popc — same ascending-i order as the old CSR, bitwise identical accumulation.
__global__ __launch_bounds__(256) void k_merge(const float* __restrict__ X, float* __restrict__ out, int b0) {
    __shared__ int s_dst[NE];
    __shared__ int s_list[NE];
    __shared__ int s_cnt;
    const int b = blockIdx.y + b0, row = blockIdx.x, t = threadIdx.x;
    float* orow = out + ((size_t)b * TOUT + row) * Cn;
    const float* Xb = X + (size_t)b * Tn * Cn;

    if (row == 0) {   // lone unm token = original token 0 (uniform early exit)
        *(float4*)(orow + t * 4) = *(const float4*)(Xb + t * 4);
        return;
    }
    const int j = row - 1;
    for (int k = t; k < NE; k += 256) s_dst[k] = g_dst[b * NE + k];
    __syncthreads();
    if (t < 32) {
        int base = 0;
        #pragma unroll
        for (int q = 0; q < 9; q++) {
            const unsigned mm = __ballot_sync(0xffffffffu, s_dst[q * 32 + t] == j);
            const int pre = __popc(mm & ((1u << t) - 1u));
            if (mm & (1u << t)) s_list[base + pre] = q * 32 + t;   // ascending i
            base += __popc(mm);
        }
        if (t == 0) s_cnt = base;
    }
    __syncthreads();
    const int cnt = s_cnt;

    float4 a = *(const float4*)(Xb + (size_t)(2 * j + 1) * Cn + t * 4);
    for (int s = 0; s < cnt; s++) {
        const int i = s_list[s];                                   // ascending i -> fixed fp order
        const float4 v = *(const float4*)(Xb + (size_t)(2 * (i + 1)) * Cn + t * 4);
        a.x += v.x; a.y += v.y; a.z += v.z; a.w += v.w;
    }
    const float inv = 1.0f / (float)(cnt + 1);
    a.x *= inv; a.y *= inv; a.z *= inv; a.w *= inv;
    *(float4*)(orow + t * 4) = a;
}

// ---------------- launch: 2-chunk two-stream pipeline (R14-proven) ----------------
extern "C" void kernel_launch(void* const* d_in, const int* in_sizes, int n_in,
                              void* d_out, int out_size) {
    const float* X = (const float*)d_in[0];
    float* out = (float*)d_out;

    static cudaStream_t s2 = nullptr;
    static cudaEvent_t evG[2], evJ;
    if (!s2) {
        cudaStreamCreateWithFlags(&s2, cudaStreamNonBlocking);
        for (int c = 0; c < 2; c++) cudaEventCreateWithFlags(&evG[c], cudaEventDisableTiming);
        cudaEventCreateWithFlags(&evJ, cudaEventDisableTiming);
    }

    for (int c = 0; c < 2; c++) {
        const int b0 = c * BCHUNK;
        k_gemm<<<dim3(3, 3, BCHUNK), 256>>>(X, b0);
        cudaEventRecord(evG[c], 0);                       // fork point on capture stream
        cudaStreamWaitEvent(s2, evG[c], 0);
        k_filter_exact<<<BCHUNK * 36, 256, 0, s2>>>(X, b0);
        k_merge       <<<dim3(TOUT, BCHUNK), 256, 0, s2>>>(X, out, b0);
    }
    cudaEventRecord(evJ, s2);                             // join s2 back
    cudaStreamWaitEvent(0, evJ, 0);
}